// round 1
// baseline (speedup 1.0000x reference)
#include <cuda_runtime.h>
#include <math.h>

#define NLAYERS 16
#define DMODEL 960
#define HQ 15
#define HKV 5
#define DH 64
#define FF 2560
#define BATCH 2
#define SEQ 1024
#define MROWS (BATCH*SEQ)   // 2048
#define QDIM (HQ*DH)        // 960
#define KVDIM (HKV*DH)      // 320

// ---------------- scratch (no allocations allowed) ----------------
__device__ float g_hn  [MROWS*DMODEL];
__device__ float g_q   [MROWS*QDIM];
__device__ float g_k   [MROWS*KVDIM];
__device__ float g_v   [MROWS*KVDIM];
__device__ float g_attn[MROWS*QDIM];
__device__ float g_gate[MROWS*FF];
__device__ float g_up  [MROWS*FF];

// ---------------- RMSNorm ----------------
__global__ void rmsnorm_kernel(const float* __restrict__ x,
                               const float* __restrict__ w,
                               float* __restrict__ out) {
    int row = blockIdx.x;
    const float* xr = x + (size_t)row * DMODEL;
    float ss = 0.f;
    for (int i = threadIdx.x; i < DMODEL; i += blockDim.x) {
        float v = xr[i];
        ss += v * v;
    }
    __shared__ float red[32];
    #pragma unroll
    for (int o = 16; o; o >>= 1) ss += __shfl_xor_sync(0xffffffffu, ss, o);
    int wid = threadIdx.x >> 5, lid = threadIdx.x & 31;
    if (lid == 0) red[wid] = ss;
    __syncthreads();
    if (wid == 0) {
        float v = (lid < (blockDim.x >> 5)) ? red[lid] : 0.f;
        #pragma unroll
        for (int o = 16; o; o >>= 1) v += __shfl_xor_sync(0xffffffffu, v, o);
        if (lid == 0) red[0] = rsqrtf(v / (float)DMODEL + 1e-5f);
    }
    __syncthreads();
    float inv = red[0];
    for (int i = threadIdx.x; i < DMODEL; i += blockDim.x)
        out[(size_t)row * DMODEL + i] = xr[i] * inv * w[i];
}

// ---------------- GEMM: C[M,N] = A[M,K] @ B[K,N]  (optionally +=) ----
// BM=128, BN=64, BK=16, 256 threads, thread tile 8x4.
template <int ADD>
__global__ __launch_bounds__(256)
void gemm_kernel(const float* __restrict__ A, const float* __restrict__ Bm,
                 float* __restrict__ C, int M, int N, int K) {
    __shared__ float As[16][128];
    __shared__ float Bs[16][64];
    int tid = threadIdx.x;
    int tx = tid & 15, ty = tid >> 4;
    int brow = blockIdx.y * 128;
    int bcol = blockIdx.x * 64;
    float acc[8][4];
    #pragma unroll
    for (int i = 0; i < 8; i++)
        #pragma unroll
        for (int j = 0; j < 4; j++) acc[i][j] = 0.f;

    const float* Aptr = A + (size_t)brow * K;
    const float* Bptr = Bm + bcol;

    for (int k0 = 0; k0 < K; k0 += 16) {
        // A tile 128x16 -> transposed smem
        #pragma unroll
        for (int i = 0; i < 2; i++) {
            int idx = tid + i * 256;     // 0..511 float4 units
            int r = idx >> 2;
            int c4 = idx & 3;
            float4 a = *(const float4*)(Aptr + (size_t)r * K + k0 + c4 * 4);
            As[c4 * 4 + 0][r] = a.x;
            As[c4 * 4 + 1][r] = a.y;
            As[c4 * 4 + 2][r] = a.z;
            As[c4 * 4 + 3][r] = a.w;
        }
        // B tile 16x64
        {
            int kr = tid >> 4, c4 = tid & 15;
            float4 b = *(const float4*)(Bptr + (size_t)(k0 + kr) * N + c4 * 4);
            *(float4*)&Bs[kr][c4 * 4] = b;
        }
        __syncthreads();
        #pragma unroll
        for (int kk = 0; kk < 16; kk++) {
            float a[8], b[4];
            *(float4*)&a[0] = *(float4*)&As[kk][ty * 8];
            *(float4*)&a[4] = *(float4*)&As[kk][ty * 8 + 4];
            *(float4*)&b[0] = *(float4*)&Bs[kk][tx * 4];
            #pragma unroll
            for (int i = 0; i < 8; i++)
                #pragma unroll
                for (int j = 0; j < 4; j++)
                    acc[i][j] += a[i] * b[j];
        }
        __syncthreads();
    }
    #pragma unroll
    for (int i = 0; i < 8; i++) {
        int r = brow + ty * 8 + i;
        #pragma unroll
        for (int j = 0; j < 4; j++) {
            int c = bcol + tx * 4 + j;
            size_t o = (size_t)r * N + c;
            if (ADD) C[o] += acc[i][j];
            else     C[o]  = acc[i][j];
        }
    }
}

// ---------------- RoPE (in place) ----------------
__global__ void rope_kernel(float* __restrict__ x, const int* __restrict__ pos, int H) {
    int idx = blockIdx.x * blockDim.x + threadIdx.x;
    int total = MROWS * H * 32;
    if (idx >= total) return;
    int d = idx & 31;
    int h = (idx >> 5) % H;
    int row = idx / (32 * H);
    float p = (float)pos[row];
    // timescale = 10000^(d/32); radians = p / timescale
    float r = p * exp2f((float)d * -0.41524101186098285f);  // -log2(10000)/32
    float sn, cs;
    sincosf(r, &sn, &cs);
    size_t base = (size_t)row * (H * DH) + h * DH + d;
    float x1 = x[base];
    float x2 = x[base + 32];
    x[base]      = x1 * cs - x2 * sn;
    x[base + 32] = x2 * cs + x1 * sn;
}

// ---------------- Flash attention (causal, GQA rep=3) ----------------
// Block: 256 threads = 8 warps; warp w handles q row blockIdx.x*8 + w.
// K/V tiles of 64 rows staged in SMEM.
__global__ __launch_bounds__(256)
void attn_kernel(const float* __restrict__ q, const float* __restrict__ k,
                 const float* __restrict__ v, float* __restrict__ out) {
    __shared__ float Ks[64][64];
    __shared__ float Vs[64][64];
    int bh = blockIdx.y;
    int b = bh / HQ, hq = bh % HQ, hk = hq / (HQ / HKV);
    int warp = threadIdx.x >> 5, lane = threadIdx.x & 31;
    int i = blockIdx.x * 8 + warp;

    const float* qp = q + (size_t)(b * SEQ + i) * QDIM + hq * DH;
    float q0 = qp[lane], q1 = qp[lane + 32];

    float m = -1e30f, lsum = 0.f, acc0 = 0.f, acc1 = 0.f;
    int ntiles = (blockIdx.x * 8) / 64 + 1;   // all 8 rows share the same tile count

    for (int t = 0; t < ntiles; t++) {
        __syncthreads();
        for (int idx = threadIdx.x; idx < 64 * 16; idx += 256) {
            int r = idx >> 4, c4 = idx & 15;
            size_t gro = (size_t)(b * SEQ + t * 64 + r) * KVDIM + hk * DH + c4 * 4;
            *(float4*)&Ks[r][c4 * 4] = *(const float4*)(k + gro);
            *(float4*)&Vs[r][c4 * 4] = *(const float4*)(v + gro);
        }
        __syncthreads();
        int jmax = min(64, i - t * 64 + 1);
        for (int jj = 0; jj < jmax; jj++) {
            float s = q0 * Ks[jj][lane] + q1 * Ks[jj][lane + 32];
            #pragma unroll
            for (int o = 16; o; o >>= 1) s += __shfl_xor_sync(0xffffffffu, s, o);
            s *= 0.125f;  // DH^-0.5
            float mn = fmaxf(m, s);
            float corr = __expf(m - mn);
            float p = __expf(s - mn);
            lsum = lsum * corr + p;
            acc0 = acc0 * corr + p * Vs[jj][lane];
            acc1 = acc1 * corr + p * Vs[jj][lane + 32];
            m = mn;
        }
    }
    float invl = 1.f / lsum;
    float* op = out + (size_t)(b * SEQ + i) * QDIM + hq * DH;
    op[lane]      = acc0 * invl;
    op[lane + 32] = acc1 * invl;
}

// ---------------- SiLU(gate) * up -> gate ----------------
__global__ void silu_mul_kernel(float* __restrict__ gate, const float* __restrict__ up, int n) {
    for (int i = blockIdx.x * blockDim.x + threadIdx.x; i < n; i += gridDim.x * blockDim.x) {
        float g = gate[i];
        float u = up[i];
        gate[i] = (g / (1.f + expf(-g))) * u;
    }
}

// ---------------- host driver ----------------
extern "C" void kernel_launch(void* const* d_in, const int* in_sizes, int n_in,
                              void* d_out, int out_size) {
    (void)in_sizes; (void)n_in; (void)out_size;
    const float* prefix = (const float*)d_in[0];
    const float* ln1    = (const float*)d_in[1];
    const float* wq     = (const float*)d_in[2];
    const float* wk     = (const float*)d_in[3];
    const float* wv     = (const float*)d_in[4];
    const float* wo     = (const float*)d_in[5];
    const float* ln2    = (const float*)d_in[6];
    const float* wg     = (const float*)d_in[7];
    const float* wu     = (const float*)d_in[8];
    const float* wd     = (const float*)d_in[9];
    const int*   pos    = (const int*)d_in[11];
    float* h = (float*)d_out;

    float *hn, *q, *k, *v, *attn, *gate, *up;
    cudaGetSymbolAddress((void**)&hn,   g_hn);
    cudaGetSymbolAddress((void**)&q,    g_q);
    cudaGetSymbolAddress((void**)&k,    g_k);
    cudaGetSymbolAddress((void**)&v,    g_v);
    cudaGetSymbolAddress((void**)&attn, g_attn);
    cudaGetSymbolAddress((void**)&gate, g_gate);
    cudaGetSymbolAddress((void**)&up,   g_up);

    cudaMemcpyAsync(h, prefix, (size_t)MROWS * DMODEL * sizeof(float),
                    cudaMemcpyDeviceToDevice, 0);

    dim3 gq(QDIM / 64, MROWS / 128);     // (15,16)
    dim3 gkv(KVDIM / 64, MROWS / 128);   // (5,16)
    dim3 gff(FF / 64, MROWS / 128);      // (40,16)
    dim3 go(DMODEL / 64, MROWS / 128);   // (15,16)

    for (int l = 0; l < NLAYERS; l++) {
        rmsnorm_kernel<<<MROWS, 256>>>(h, ln1 + (size_t)l * DMODEL, hn);
        gemm_kernel<0><<<gq,  256>>>(hn, wq + (size_t)l * DMODEL * QDIM,  q, MROWS, QDIM,  DMODEL);
        gemm_kernel<0><<<gkv, 256>>>(hn, wk + (size_t)l * DMODEL * KVDIM, k, MROWS, KVDIM, DMODEL);
        gemm_kernel<0><<<gkv, 256>>>(hn, wv + (size_t)l * DMODEL * KVDIM, v, MROWS, KVDIM, DMODEL);
        rope_kernel<<<(MROWS * HQ * 32 + 255) / 256, 256>>>(q, pos, HQ);
        rope_kernel<<<(MROWS * HKV * 32 + 255) / 256, 256>>>(k, pos, HKV);
        attn_kernel<<<dim3(SEQ / 8, BATCH * HQ), 256>>>(q, k, v, attn);
        gemm_kernel<1><<<go,  256>>>(attn, wo + (size_t)l * QDIM * DMODEL, h, MROWS, DMODEL, QDIM);
        rmsnorm_kernel<<<MROWS, 256>>>(h, ln2 + (size_t)l * DMODEL, hn);
        gemm_kernel<0><<<gff, 256>>>(hn, wg + (size_t)l * DMODEL * FF, gate, MROWS, FF, DMODEL);
        gemm_kernel<0><<<gff, 256>>>(hn, wu + (size_t)l * DMODEL * FF, up,   MROWS, FF, DMODEL);
        silu_mul_kernel<<<2048, 256>>>(gate, up, MROWS * FF);
        gemm_kernel<1><<<go,  256>>>(gate, wd + (size_t)l * FF * DMODEL, h, MROWS, DMODEL, FF);
    }
}

// round 3
// speedup vs baseline: 1.6723x; 1.6723x over previous
#include <cuda_runtime.h>
#include <cuda_bf16.h>
#include <math.h>
#include <stdint.h>

#define NLAYERS 16
#define DMODEL 960
#define HQ 15
#define HKV 5
#define DH 64
#define FF 2560
#define BATCH 2
#define SEQ 1024
#define MROWS (BATCH*SEQ)   // 2048
#define QDIM (HQ*DH)        // 960
#define KVDIM (HKV*DH)      // 320
#define QKVN (QDIM + 2*KVDIM) // 1600

// ---------------- scratch (no allocations allowed) ----------------
__device__ __nv_bfloat16 g_hn_h[MROWS*DMODEL];
__device__ __nv_bfloat16 g_hn_l[MROWS*DMODEL];
__device__ float         g_qkv [MROWS*QKVN];
__device__ __nv_bfloat16 g_at_h[MROWS*QDIM];
__device__ __nv_bfloat16 g_at_l[MROWS*QDIM];
__device__ float         g_gu  [MROWS*2*FF];
__device__ __nv_bfloat16 g_ac_h[MROWS*FF];
__device__ __nv_bfloat16 g_ac_l[MROWS*FF];
// transposed split weights (per layer, [N][K] row-major bf16)
__device__ __nv_bfloat16 g_wqkv_h[QKVN*DMODEL];
__device__ __nv_bfloat16 g_wqkv_l[QKVN*DMODEL];
__device__ __nv_bfloat16 g_wo_h [DMODEL*QDIM];
__device__ __nv_bfloat16 g_wo_l [DMODEL*QDIM];
__device__ __nv_bfloat16 g_wgu_h[2*FF*DMODEL];
__device__ __nv_bfloat16 g_wgu_l[2*FF*DMODEL];
__device__ __nv_bfloat16 g_wd_h [DMODEL*FF];
__device__ __nv_bfloat16 g_wd_l [DMODEL*FF];

// ---------------- warp-mma helpers (generic PTX, sm_80+) ----------------
__device__ __forceinline__ uint32_t smem_u32(const void* p) {
    uint32_t a;
    asm("{ .reg .u64 t; cvta.to.shared.u64 t, %1; cvt.u32.u64 %0, t; }" : "=r"(a) : "l"(p));
    return a;
}
__device__ __forceinline__ void ldm4(uint32_t* r, uint32_t addr) {
    asm volatile("ldmatrix.sync.aligned.m8n8.x4.shared.b16 {%0,%1,%2,%3}, [%4];"
        : "=r"(r[0]), "=r"(r[1]), "=r"(r[2]), "=r"(r[3]) : "r"(addr));
}
__device__ __forceinline__ void mma16816(float* c, const uint32_t* a, const uint32_t* b) {
    asm volatile("mma.sync.aligned.m16n8k16.row.col.f32.bf16.bf16.f32 "
        "{%0,%1,%2,%3}, {%4,%5,%6,%7}, {%8,%9}, {%0,%1,%2,%3};"
        : "+f"(c[0]), "+f"(c[1]), "+f"(c[2]), "+f"(c[3])
        : "r"(a[0]), "r"(a[1]), "r"(a[2]), "r"(a[3]), "r"(b[0]), "r"(b[1]));
}

// ---------------- mma GEMM: C[M,N] (+)= A[M,K] @ Bt[N,K]^T --------------
// A split (hi/lo bf16 [M,K]), Bt split (hi/lo bf16 [N,K]). 128x64 tile/CTA, BK=64.
// 8 warps: warp_m in {0,1} (64 rows), warp_n in {0..3} (16 cols = 2 n8 tiles).
#define ASTR 72   // 64 + 8 pad (bf16 elems): 144B row stride, conflict-free ldmatrix
#define SM_A_ELEMS (128*ASTR)
#define SM_B_ELEMS (64*ASTR)
#define GEMM_SMEM ((2*SM_A_ELEMS + 2*SM_B_ELEMS)*2)  // 55296 bytes

template <int ADD>
__global__ __launch_bounds__(256, 2)
void mma_gemm(const __nv_bfloat16* __restrict__ Ah, const __nv_bfloat16* __restrict__ Al,
              const __nv_bfloat16* __restrict__ Bh, const __nv_bfloat16* __restrict__ Bl,
              float* __restrict__ C, int N, int K) {
    extern __shared__ __nv_bfloat16 sm[];
    __nv_bfloat16* sAh = sm;
    __nv_bfloat16* sAl = sAh + SM_A_ELEMS;
    __nv_bfloat16* sBh = sAl + SM_A_ELEMS;
    __nv_bfloat16* sBl = sBh + SM_B_ELEMS;

    int tid = threadIdx.x, wid = tid >> 5, lane = tid & 31;
    int brow = blockIdx.y * 128, bcol = blockIdx.x * 64;
    int warp_m = wid >> 2, warp_n = wid & 3;

    float acc[4][2][4];
    #pragma unroll
    for (int mt = 0; mt < 4; mt++)
        #pragma unroll
        for (int nt = 0; nt < 2; nt++)
            #pragma unroll
            for (int i = 0; i < 4; i++) acc[mt][nt][i] = 0.f;

    // precomputed ldmatrix lane offsets (element units)
    int a_r = (lane & 15), a_k = (lane >> 4) * 8;               // A: row, kcol within tile
    int b_n = warp_n * 16 + (lane & 7) + ((lane >> 4) << 3);    // B: n row
    int b_k = ((lane >> 3) & 1) * 8;                            // B: kcol within k16

    for (int k0 = 0; k0 < K; k0 += 64) {
        __syncthreads();
        // A tiles: 128 rows x 64 cols, 8 x uint4 per row, hi+lo
        #pragma unroll 4
        for (int u = tid; u < 1024; u += 256) {
            int r = u >> 3, c = (u & 7) * 8;
            size_t g = (size_t)(brow + r) * K + k0 + c;
            *(uint4*)&sAh[r * ASTR + c] = *(const uint4*)(Ah + g);
            *(uint4*)&sAl[r * ASTR + c] = *(const uint4*)(Al + g);
        }
        // B tiles: 64 rows x 64 cols
        #pragma unroll 2
        for (int u = tid; u < 512; u += 256) {
            int r = u >> 3, c = (u & 7) * 8;
            size_t g = (size_t)(bcol + r) * K + k0 + c;
            *(uint4*)&sBh[r * ASTR + c] = *(const uint4*)(Bh + g);
            *(uint4*)&sBl[r * ASTR + c] = *(const uint4*)(Bl + g);
        }
        __syncthreads();

        #pragma unroll
        for (int kk = 0; kk < 4; kk++) {
            int ko = kk * 16;
            uint32_t bh[4], bl[4];
            ldm4(bh, smem_u32(&sBh[b_n * ASTR + ko + b_k]));
            ldm4(bl, smem_u32(&sBl[b_n * ASTR + ko + b_k]));
            #pragma unroll
            for (int mt = 0; mt < 4; mt++) {
                int r = (warp_m * 64 + mt * 16 + a_r) * ASTR + ko + a_k;
                uint32_t ah[4], al[4];
                ldm4(ah, smem_u32(&sAh[r]));
                ldm4(al, smem_u32(&sAl[r]));
                #pragma unroll
                for (int nt = 0; nt < 2; nt++) {
                    mma16816(acc[mt][nt], ah, bh + 2 * nt);
                    mma16816(acc[mt][nt], ah, bl + 2 * nt);
                    mma16816(acc[mt][nt], al, bh + 2 * nt);
                }
            }
        }
    }

    // epilogue
    #pragma unroll
    for (int mt = 0; mt < 4; mt++) {
        int r0 = brow + warp_m * 64 + mt * 16 + (lane >> 2);
        #pragma unroll
        for (int nt = 0; nt < 2; nt++) {
            int c0 = bcol + warp_n * 16 + nt * 8 + (lane & 3) * 2;
            float* p0 = C + (size_t)r0 * N + c0;
            float* p1 = p0 + 8 * (size_t)N;
            if (ADD) {
                p0[0] += acc[mt][nt][0]; p0[1] += acc[mt][nt][1];
                p1[0] += acc[mt][nt][2]; p1[1] += acc[mt][nt][3];
            } else {
                *(float2*)p0 = make_float2(acc[mt][nt][0], acc[mt][nt][1]);
                *(float2*)p1 = make_float2(acc[mt][nt][2], acc[mt][nt][3]);
            }
        }
    }
}

// ---------------- weight transpose + bf16 split: W[K][N] -> T{h,l}[N][K] ----------------
__global__ void wt_split(const float* __restrict__ W, __nv_bfloat16* __restrict__ Th,
                         __nv_bfloat16* __restrict__ Tl, int K, int N, int ldt) {
    __shared__ float t[32][33];
    int k0 = blockIdx.y * 32, n0 = blockIdx.x * 32;
    int tx = threadIdx.x, ty = threadIdx.y;
    #pragma unroll
    for (int j = 0; j < 4; j++)
        t[ty + 8 * j][tx] = W[(size_t)(k0 + ty + 8 * j) * N + n0 + tx];
    __syncthreads();
    #pragma unroll
    for (int j = 0; j < 4; j++) {
        int n = ty + 8 * j, k = tx;
        float v = t[k][n];
        __nv_bfloat16 h = __float2bfloat16(v);
        Th[(size_t)(n0 + n) * ldt + k0 + k] = h;
        Tl[(size_t)(n0 + n) * ldt + k0 + k] = __float2bfloat16(v - __bfloat162float(h));
    }
}

// ---------------- RMSNorm with fused bf16 split ----------------
__global__ void rmsnorm_split(const float* __restrict__ x, const float* __restrict__ w,
                              __nv_bfloat16* __restrict__ oh, __nv_bfloat16* __restrict__ ol) {
    int row = blockIdx.x;
    const float* xr = x + (size_t)row * DMODEL;
    float ss = 0.f;
    for (int i = threadIdx.x; i < DMODEL; i += blockDim.x) {
        float v = xr[i];
        ss += v * v;
    }
    __shared__ float red[32];
    #pragma unroll
    for (int o = 16; o; o >>= 1) ss += __shfl_xor_sync(0xffffffffu, ss, o);
    int wid = threadIdx.x >> 5, lid = threadIdx.x & 31;
    if (lid == 0) red[wid] = ss;
    __syncthreads();
    if (wid == 0) {
        float v = (lid < (blockDim.x >> 5)) ? red[lid] : 0.f;
        #pragma unroll
        for (int o = 16; o; o >>= 1) v += __shfl_xor_sync(0xffffffffu, v, o);
        if (lid == 0) red[0] = rsqrtf(v / (float)DMODEL + 1e-5f);
    }
    __syncthreads();
    float inv = red[0];
    for (int i = threadIdx.x; i < DMODEL; i += blockDim.x) {
        float y = xr[i] * inv * w[i];
        __nv_bfloat16 h = __float2bfloat16(y);
        oh[(size_t)row * DMODEL + i] = h;
        ol[(size_t)row * DMODEL + i] = __float2bfloat16(y - __bfloat162float(h));
    }
}

// ---------------- RoPE (in place, on qkv buffer, stride QKVN) ----------------
__global__ void rope_kernel(float* __restrict__ x, const int* __restrict__ pos, int H, int coff) {
    int idx = blockIdx.x * blockDim.x + threadIdx.x;
    int total = MROWS * H * 32;
    if (idx >= total) return;
    int d = idx & 31;
    int h = (idx >> 5) % H;
    int row = idx / (32 * H);
    float p = (float)pos[row];
    float r = p * exp2f((float)d * -0.41524101186098285f);  // -log2(10000)/32
    float sn, cs;
    sincosf(r, &sn, &cs);
    size_t base = (size_t)row * QKVN + coff + h * DH + d;
    float x1 = x[base];
    float x2 = x[base + 32];
    x[base]      = x1 * cs - x2 * sn;
    x[base + 32] = x2 * cs + x1 * sn;
}

// ---------------- Flash attention (causal, GQA) with fused split epilogue ----------------
__global__ __launch_bounds__(256)
void attn_kernel(const float* __restrict__ qkv,
                 __nv_bfloat16* __restrict__ oh, __nv_bfloat16* __restrict__ ol) {
    __shared__ float Ks[64][64];
    __shared__ float Vs[64][64];
    int bh = blockIdx.y;
    int b = bh / HQ, hq = bh % HQ, hk = hq / (HQ / HKV);
    int warp = threadIdx.x >> 5, lane = threadIdx.x & 31;
    int i = blockIdx.x * 8 + warp;

    const float* qp = qkv + (size_t)(b * SEQ + i) * QKVN + hq * DH;
    float q0 = qp[lane], q1 = qp[lane + 32];

    float m = -1e30f, lsum = 0.f, acc0 = 0.f, acc1 = 0.f;
    int ntiles = (blockIdx.x * 8) / 64 + 1;

    for (int t = 0; t < ntiles; t++) {
        __syncthreads();
        for (int idx = threadIdx.x; idx < 64 * 16; idx += 256) {
            int r = idx >> 4, c4 = idx & 15;
            size_t gro = (size_t)(b * SEQ + t * 64 + r) * QKVN + hk * DH + c4 * 4;
            *(float4*)&Ks[r][c4 * 4] = *(const float4*)(qkv + gro + QDIM);
            *(float4*)&Vs[r][c4 * 4] = *(const float4*)(qkv + gro + QDIM + KVDIM);
        }
        __syncthreads();
        int jmax = min(64, i - t * 64 + 1);
        for (int jj = 0; jj < jmax; jj++) {
            float s = q0 * Ks[jj][lane] + q1 * Ks[jj][lane + 32];
            #pragma unroll
            for (int o = 16; o; o >>= 1) s += __shfl_xor_sync(0xffffffffu, s, o);
            s *= 0.125f;
            float mn = fmaxf(m, s);
            float corr = __expf(m - mn);
            float p = __expf(s - mn);
            lsum = lsum * corr + p;
            acc0 = acc0 * corr + p * Vs[jj][lane];
            acc1 = acc1 * corr + p * Vs[jj][lane + 32];
            m = mn;
        }
    }
    float invl = 1.f / lsum;
    float o0 = acc0 * invl, o1 = acc1 * invl;
    size_t ob = (size_t)(b * SEQ + i) * QDIM + hq * DH;
    __nv_bfloat16 h0 = __float2bfloat16(o0), h1 = __float2bfloat16(o1);
    oh[ob + lane]      = h0;
    ol[ob + lane]      = __float2bfloat16(o0 - __bfloat162float(h0));
    oh[ob + lane + 32] = h1;
    ol[ob + lane + 32] = __float2bfloat16(o1 - __bfloat162float(h1));
}

// ---------------- SiLU(gate)*up with fused bf16 split ----------------
__global__ void silu_split(const float* __restrict__ gu,
                           __nv_bfloat16* __restrict__ oh, __nv_bfloat16* __restrict__ ol) {
    int n = MROWS * FF;
    for (int i = blockIdx.x * blockDim.x + threadIdx.x; i < n; i += gridDim.x * blockDim.x) {
        int r = i / FF, c = i - r * FF;
        float g = gu[(size_t)r * (2 * FF) + c];
        float u = gu[(size_t)r * (2 * FF) + FF + c];
        float y = (g / (1.f + __expf(-g))) * u;
        __nv_bfloat16 h = __float2bfloat16(y);
        oh[i] = h;
        ol[i] = __float2bfloat16(y - __bfloat162float(h));
    }
}

// ---------------- host driver ----------------
extern "C" void kernel_launch(void* const* d_in, const int* in_sizes, int n_in,
                              void* d_out, int out_size) {
    (void)in_sizes; (void)n_in; (void)out_size;
    const float* prefix = (const float*)d_in[0];
    const float* ln1    = (const float*)d_in[1];
    const float* wq     = (const float*)d_in[2];
    const float* wk     = (const float*)d_in[3];
    const float* wv     = (const float*)d_in[4];
    const float* wo     = (const float*)d_in[5];
    const float* ln2    = (const float*)d_in[6];
    const float* wg     = (const float*)d_in[7];
    const float* wu     = (const float*)d_in[8];
    const float* wd     = (const float*)d_in[9];
    const int*   pos    = (const int*)d_in[11];
    float* h = (float*)d_out;

    __nv_bfloat16 *hn_h, *hn_l, *at_h, *at_l, *ac_h, *ac_l;
    __nv_bfloat16 *wqkv_h, *wqkv_l, *wo_h, *wo_l, *wgu_h, *wgu_l, *wd_h, *wd_l;
    float *qkv, *gu;
    cudaGetSymbolAddress((void**)&hn_h, g_hn_h);
    cudaGetSymbolAddress((void**)&hn_l, g_hn_l);
    cudaGetSymbolAddress((void**)&qkv,  g_qkv);
    cudaGetSymbolAddress((void**)&at_h, g_at_h);
    cudaGetSymbolAddress((void**)&at_l, g_at_l);
    cudaGetSymbolAddress((void**)&gu,   g_gu);
    cudaGetSymbolAddress((void**)&ac_h, g_ac_h);
    cudaGetSymbolAddress((void**)&ac_l, g_ac_l);
    cudaGetSymbolAddress((void**)&wqkv_h, g_wqkv_h);
    cudaGetSymbolAddress((void**)&wqkv_l, g_wqkv_l);
    cudaGetSymbolAddress((void**)&wo_h,   g_wo_h);
    cudaGetSymbolAddress((void**)&wo_l,   g_wo_l);
    cudaGetSymbolAddress((void**)&wgu_h,  g_wgu_h);
    cudaGetSymbolAddress((void**)&wgu_l,  g_wgu_l);
    cudaGetSymbolAddress((void**)&wd_h,   g_wd_h);
    cudaGetSymbolAddress((void**)&wd_l,   g_wd_l);

    cudaFuncSetAttribute(mma_gemm<0>, cudaFuncAttributeMaxDynamicSharedMemorySize, GEMM_SMEM);
    cudaFuncSetAttribute(mma_gemm<1>, cudaFuncAttributeMaxDynamicSharedMemorySize, GEMM_SMEM);

    cudaMemcpyAsync(h, prefix, (size_t)MROWS * DMODEL * sizeof(float),
                    cudaMemcpyDeviceToDevice, 0);

    dim3 tb(32, 8);
    for (int l = 0; l < NLAYERS; l++) {
        const float* wq_l = wq + (size_t)l * DMODEL * QDIM;
        const float* wk_l = wk + (size_t)l * DMODEL * KVDIM;
        const float* wv_l = wv + (size_t)l * DMODEL * KVDIM;
        const float* wo_p = wo + (size_t)l * QDIM * DMODEL;
        const float* wg_l = wg + (size_t)l * DMODEL * FF;
        const float* wu_l = wu + (size_t)l * DMODEL * FF;
        const float* wd_p = wd + (size_t)l * FF * DMODEL;

        // weight transpose + split (into [N][K] bf16 hi/lo)
        wt_split<<<dim3(QDIM / 32, DMODEL / 32), tb>>>(wq_l, wqkv_h, wqkv_l, DMODEL, QDIM, DMODEL);
        wt_split<<<dim3(KVDIM / 32, DMODEL / 32), tb>>>(wk_l, wqkv_h + (size_t)QDIM * DMODEL,
                                                        wqkv_l + (size_t)QDIM * DMODEL, DMODEL, KVDIM, DMODEL);
        wt_split<<<dim3(KVDIM / 32, DMODEL / 32), tb>>>(wv_l, wqkv_h + (size_t)(QDIM + KVDIM) * DMODEL,
                                                        wqkv_l + (size_t)(QDIM + KVDIM) * DMODEL, DMODEL, KVDIM, DMODEL);
        wt_split<<<dim3(DMODEL / 32, QDIM / 32), tb>>>(wo_p, wo_h, wo_l, QDIM, DMODEL, QDIM);
        wt_split<<<dim3(FF / 32, DMODEL / 32), tb>>>(wg_l, wgu_h, wgu_l, DMODEL, FF, DMODEL);
        wt_split<<<dim3(FF / 32, DMODEL / 32), tb>>>(wu_l, wgu_h + (size_t)FF * DMODEL,
                                                     wgu_l + (size_t)FF * DMODEL, DMODEL, FF, DMODEL);
        wt_split<<<dim3(DMODEL / 32, FF / 32), tb>>>(wd_p, wd_h, wd_l, FF, DMODEL, FF);

        // attention block
        rmsnorm_split<<<MROWS, 256>>>(h, ln1 + (size_t)l * DMODEL, hn_h, hn_l);
        mma_gemm<0><<<dim3(QKVN / 64, MROWS / 128), 256, GEMM_SMEM>>>(hn_h, hn_l, wqkv_h, wqkv_l, qkv, QKVN, DMODEL);
        rope_kernel<<<(MROWS * HQ * 32 + 255) / 256, 256>>>(qkv, pos, HQ, 0);
        rope_kernel<<<(MROWS * HKV * 32 + 255) / 256, 256>>>(qkv, pos, HKV, QDIM);
        attn_kernel<<<dim3(SEQ / 8, BATCH * HQ), 256>>>(qkv, at_h, at_l);
        mma_gemm<1><<<dim3(DMODEL / 64, MROWS / 128), 256, GEMM_SMEM>>>(at_h, at_l, wo_h, wo_l, h, DMODEL, QDIM);

        // mlp block
        rmsnorm_split<<<MROWS, 256>>>(h, ln2 + (size_t)l * DMODEL, hn_h, hn_l);
        mma_gemm<0><<<dim3(2 * FF / 64, MROWS / 128), 256, GEMM_SMEM>>>(hn_h, hn_l, wgu_h, wgu_l, gu, 2 * FF, DMODEL);
        silu_split<<<2048, 256>>>(gu, ac_h, ac_l);
        mma_gemm<1><<<dim3(DMODEL / 64, MROWS / 128), 256, GEMM_SMEM>>>(ac_h, ac_l, wd_h, wd_l, h, DMODEL, FF);
    }
}

// round 4
// speedup vs baseline: 1.8406x; 1.1006x over previous
#include <cuda_runtime.h>
#include <cuda_bf16.h>
#include <math.h>
#include <stdint.h>

#define NLAYERS 16
#define DMODEL 960
#define HQ 15
#define HKV 5
#define DH 64
#define FF 2560
#define BATCH 2
#define SEQ 1024
#define MROWS (BATCH*SEQ)   // 2048
#define QDIM (HQ*DH)        // 960
#define KVDIM (HKV*DH)      // 320
#define QKVN (QDIM + 2*KVDIM) // 1600

// ---------------- scratch (no allocations allowed) ----------------
__device__ __nv_bfloat16 g_hn_h[MROWS*DMODEL];
__device__ __nv_bfloat16 g_hn_l[MROWS*DMODEL];
__device__ float         g_qkv [MROWS*QKVN];
__device__ __nv_bfloat16 g_at_h[MROWS*QDIM];
__device__ __nv_bfloat16 g_at_l[MROWS*QDIM];
__device__ float         g_gu  [MROWS*2*FF];
__device__ __nv_bfloat16 g_ac_h[MROWS*FF];
__device__ __nv_bfloat16 g_ac_l[MROWS*FF];
// transposed split weights (per layer, [N][K] row-major bf16)
__device__ __nv_bfloat16 g_wqkv_h[QKVN*DMODEL];
__device__ __nv_bfloat16 g_wqkv_l[QKVN*DMODEL];
__device__ __nv_bfloat16 g_wo_h [DMODEL*QDIM];
__device__ __nv_bfloat16 g_wo_l [DMODEL*QDIM];
__device__ __nv_bfloat16 g_wgu_h[2*FF*DMODEL];
__device__ __nv_bfloat16 g_wgu_l[2*FF*DMODEL];
__device__ __nv_bfloat16 g_wd_h [DMODEL*FF];
__device__ __nv_bfloat16 g_wd_l [DMODEL*FF];

// ---------------- warp-mma helpers (generic PTX, sm_80+) ----------------
__device__ __forceinline__ uint32_t smem_u32(const void* p) {
    uint32_t a;
    asm("{ .reg .u64 t; cvta.to.shared.u64 t, %1; cvt.u32.u64 %0, t; }" : "=r"(a) : "l"(p));
    return a;
}
__device__ __forceinline__ void ldm4(uint32_t* r, uint32_t addr) {
    asm volatile("ldmatrix.sync.aligned.m8n8.x4.shared.b16 {%0,%1,%2,%3}, [%4];"
        : "=r"(r[0]), "=r"(r[1]), "=r"(r[2]), "=r"(r[3]) : "r"(addr));
}
__device__ __forceinline__ void mma16816(float* c, const uint32_t* a, const uint32_t* b) {
    asm volatile("mma.sync.aligned.m16n8k16.row.col.f32.bf16.bf16.f32 "
        "{%0,%1,%2,%3}, {%4,%5,%6,%7}, {%8,%9}, {%0,%1,%2,%3};"
        : "+f"(c[0]), "+f"(c[1]), "+f"(c[2]), "+f"(c[3])
        : "r"(a[0]), "r"(a[1]), "r"(a[2]), "r"(a[3]), "r"(b[0]), "r"(b[1]));
}
__device__ __forceinline__ void cpasync16(uint32_t dst, const void* src) {
    asm volatile("cp.async.cg.shared.global [%0], [%1], 16;" :: "r"(dst), "l"(src));
}
#define CP_COMMIT() asm volatile("cp.async.commit_group;" ::: "memory")
#define CP_WAIT1()  asm volatile("cp.async.wait_group 1;" ::: "memory")
#define CP_WAIT0()  asm volatile("cp.async.wait_group 0;" ::: "memory")

// ---------------- mma GEMM: C[M,N] (+)= A[M,K] @ Bt[N,K]^T --------------
// Split bf16 hi/lo, 3-term compensated product. 128x64 CTA tile, BK=64,
// 2-stage cp.async pipeline, XOR-swizzled smem (stride 64 elems, no pad).
// Stage layout (bytes): Ah[0,16384) Al[16384,32768) Bh[32768,40960) Bl[40960,49152)
#define STAGE_B 49152
#define GEMM_SMEM (2*STAGE_B)   // 98304

template <int ADD>
__global__ __launch_bounds__(256, 2)
void mma_gemm(const __nv_bfloat16* __restrict__ Ah, const __nv_bfloat16* __restrict__ Al,
              const __nv_bfloat16* __restrict__ Bh, const __nv_bfloat16* __restrict__ Bl,
              float* __restrict__ C, int N, int K) {
    extern __shared__ __nv_bfloat16 sm[];
    uint32_t smb = smem_u32(sm);

    int tid = threadIdx.x, wid = tid >> 5, lane = tid & 31;
    int brow = blockIdx.y * 128, bcol = blockIdx.x * 64;
    int warp_m = wid >> 2, warp_n = wid & 3;

    float acc[4][2][4];
    #pragma unroll
    for (int mt = 0; mt < 4; mt++)
        #pragma unroll
        for (int nt = 0; nt < 2; nt++)
            #pragma unroll
            for (int i = 0; i < 4; i++) acc[mt][nt][i] = 0.f;

    // --- cp.async producer addressing (per thread) ---
    int tr = tid >> 3, tj = tid & 7;                 // row group, 16B chunk
    uint32_t tsw = (uint32_t)((tj ^ (tr & 7)) << 4); // swizzled chunk byte offset
    const __nv_bfloat16* gAh = Ah + (size_t)(brow + tr) * K + tj * 8;
    const __nv_bfloat16* gAl = Al + (size_t)(brow + tr) * K + tj * 8;
    const __nv_bfloat16* gBh = Bh + (size_t)(bcol + tr) * K + tj * 8;
    const __nv_bfloat16* gBl = Bl + (size_t)(bcol + tr) * K + tj * 8;

    // --- ldmatrix consumer addressing (per lane) ---
    int sxor = lane & 7;
    uint32_t aRowOff = (uint32_t)((warp_m * 64 + (lane & 15)) * 128);  // bytes
    int a_cs = lane >> 4;                                              // chunk half
    uint32_t bRowOff = (uint32_t)((warp_n * 16 + (lane & 7) + ((lane >> 4) << 3)) * 128);
    int b_cs = (lane >> 3) & 1;

    int nch = K >> 6;

    // prologue: stage 0
    {
        #pragma unroll
        for (int i = 0; i < 4; i++) {
            uint32_t d = smb + (uint32_t)((tr + 32 * i) * 128) + tsw;
            cpasync16(d,           gAh + (size_t)(32 * i) * K);
            cpasync16(d + 16384u,  gAl + (size_t)(32 * i) * K);
        }
        #pragma unroll
        for (int i = 0; i < 2; i++) {
            uint32_t d = smb + 32768u + (uint32_t)((tr + 32 * i) * 128) + tsw;
            cpasync16(d,          gBh + (size_t)(32 * i) * K);
            cpasync16(d + 8192u,  gBl + (size_t)(32 * i) * K);
        }
        CP_COMMIT();
    }

    for (int ch = 0; ch < nch; ch++) {
        uint32_t sbase = smb + (uint32_t)((ch & 1) ? STAGE_B : 0);
        if (ch + 1 < nch) {
            uint32_t nbase = smb + (uint32_t)(((ch + 1) & 1) ? STAGE_B : 0);
            int k0 = (ch + 1) << 6;
            #pragma unroll
            for (int i = 0; i < 4; i++) {
                uint32_t d = nbase + (uint32_t)((tr + 32 * i) * 128) + tsw;
                cpasync16(d,          gAh + (size_t)(32 * i) * K + k0);
                cpasync16(d + 16384u, gAl + (size_t)(32 * i) * K + k0);
            }
            #pragma unroll
            for (int i = 0; i < 2; i++) {
                uint32_t d = nbase + 32768u + (uint32_t)((tr + 32 * i) * 128) + tsw;
                cpasync16(d,         gBh + (size_t)(32 * i) * K + k0);
                cpasync16(d + 8192u, gBl + (size_t)(32 * i) * K + k0);
            }
            CP_COMMIT();
            CP_WAIT1();
        } else {
            CP_WAIT0();
        }
        __syncthreads();

        #pragma unroll
        for (int kk = 0; kk < 4; kk++) {
            uint32_t bAddr = sbase + 32768u + bRowOff + (uint32_t)((((kk * 2 + b_cs) ^ sxor)) << 4);
            uint32_t bh[4], bl[4];
            ldm4(bh, bAddr);
            ldm4(bl, bAddr + 8192u);
            uint32_t aCh = (uint32_t)((((kk * 2 + a_cs) ^ sxor)) << 4);
            #pragma unroll
            for (int mt = 0; mt < 4; mt++) {
                uint32_t aAddr = sbase + aRowOff + (uint32_t)(mt * 2048) + aCh;
                uint32_t ah[4], al[4];
                ldm4(ah, aAddr);
                ldm4(al, aAddr + 16384u);
                #pragma unroll
                for (int nt = 0; nt < 2; nt++) {
                    mma16816(acc[mt][nt], ah, bh + 2 * nt);
                    mma16816(acc[mt][nt], ah, bl + 2 * nt);
                    mma16816(acc[mt][nt], al, bh + 2 * nt);
                }
            }
        }
        __syncthreads();
    }

    // epilogue
    #pragma unroll
    for (int mt = 0; mt < 4; mt++) {
        int r0 = brow + warp_m * 64 + mt * 16 + (lane >> 2);
        #pragma unroll
        for (int nt = 0; nt < 2; nt++) {
            int c0 = bcol + warp_n * 16 + nt * 8 + (lane & 3) * 2;
            float* p0 = C + (size_t)r0 * N + c0;
            float* p1 = p0 + 8 * (size_t)N;
            if (ADD) {
                p0[0] += acc[mt][nt][0]; p0[1] += acc[mt][nt][1];
                p1[0] += acc[mt][nt][2]; p1[1] += acc[mt][nt][3];
            } else {
                *(float2*)p0 = make_float2(acc[mt][nt][0], acc[mt][nt][1]);
                *(float2*)p1 = make_float2(acc[mt][nt][2], acc[mt][nt][3]);
            }
        }
    }
}

// ---------------- weight transpose + bf16 split: W[K][N] -> T{h,l}[N][K] ----------------
__global__ void wt_split(const float* __restrict__ W, __nv_bfloat16* __restrict__ Th,
                         __nv_bfloat16* __restrict__ Tl, int K, int N, int ldt) {
    __shared__ float t[32][33];
    int k0 = blockIdx.y * 32, n0 = blockIdx.x * 32;
    int tx = threadIdx.x, ty = threadIdx.y;
    #pragma unroll
    for (int j = 0; j < 4; j++)
        t[ty + 8 * j][tx] = W[(size_t)(k0 + ty + 8 * j) * N + n0 + tx];
    __syncthreads();
    #pragma unroll
    for (int j = 0; j < 4; j++) {
        int n = ty + 8 * j, k = tx;
        float v = t[k][n];
        __nv_bfloat16 h = __float2bfloat16(v);
        Th[(size_t)(n0 + n) * ldt + k0 + k] = h;
        Tl[(size_t)(n0 + n) * ldt + k0 + k] = __float2bfloat16(v - __bfloat162float(h));
    }
}

// ---------------- RMSNorm with fused bf16 split ----------------
__global__ void rmsnorm_split(const float* __restrict__ x, const float* __restrict__ w,
                              __nv_bfloat16* __restrict__ oh, __nv_bfloat16* __restrict__ ol) {
    int row = blockIdx.x;
    const float* xr = x + (size_t)row * DMODEL;
    float ss = 0.f;
    for (int i = threadIdx.x; i < DMODEL; i += blockDim.x) {
        float v = xr[i];
        ss += v * v;
    }
    __shared__ float red[32];
    #pragma unroll
    for (int o = 16; o; o >>= 1) ss += __shfl_xor_sync(0xffffffffu, ss, o);
    int wid = threadIdx.x >> 5, lid = threadIdx.x & 31;
    if (lid == 0) red[wid] = ss;
    __syncthreads();
    if (wid == 0) {
        float v = (lid < (blockDim.x >> 5)) ? red[lid] : 0.f;
        #pragma unroll
        for (int o = 16; o; o >>= 1) v += __shfl_xor_sync(0xffffffffu, v, o);
        if (lid == 0) red[0] = rsqrtf(v / (float)DMODEL + 1e-5f);
    }
    __syncthreads();
    float inv = red[0];
    for (int i = threadIdx.x; i < DMODEL; i += blockDim.x) {
        float y = xr[i] * inv * w[i];
        __nv_bfloat16 h = __float2bfloat16(y);
        oh[(size_t)row * DMODEL + i] = h;
        ol[(size_t)row * DMODEL + i] = __float2bfloat16(y - __bfloat162float(h));
    }
}

// ---------------- RoPE (in place, on qkv buffer, stride QKVN) ----------------
__global__ void rope_kernel(float* __restrict__ x, const int* __restrict__ pos, int H, int coff) {
    int idx = blockIdx.x * blockDim.x + threadIdx.x;
    int total = MROWS * H * 32;
    if (idx >= total) return;
    int d = idx & 31;
    int h = (idx >> 5) % H;
    int row = idx / (32 * H);
    float p = (float)pos[row];
    float r = p * exp2f((float)d * -0.41524101186098285f);  // -log2(10000)/32
    float sn, cs;
    sincosf(r, &sn, &cs);
    size_t base = (size_t)row * QKVN + coff + h * DH + d;
    float x1 = x[base];
    float x2 = x[base + 32];
    x[base]      = x1 * cs - x2 * sn;
    x[base + 32] = x2 * cs + x1 * sn;
}

// ---------------- Flash attention (causal, GQA) with fused split epilogue ----------------
__global__ __launch_bounds__(256)
void attn_kernel(const float* __restrict__ qkv,
                 __nv_bfloat16* __restrict__ oh, __nv_bfloat16* __restrict__ ol) {
    __shared__ float Ks[64][64];
    __shared__ float Vs[64][64];
    int bh = blockIdx.y;
    int b = bh / HQ, hq = bh % HQ, hk = hq / (HQ / HKV);
    int warp = threadIdx.x >> 5, lane = threadIdx.x & 31;
    int i = blockIdx.x * 8 + warp;

    const float* qp = qkv + (size_t)(b * SEQ + i) * QKVN + hq * DH;
    float q0 = qp[lane], q1 = qp[lane + 32];

    float m = -1e30f, lsum = 0.f, acc0 = 0.f, acc1 = 0.f;
    int ntiles = (blockIdx.x * 8) / 64 + 1;

    for (int t = 0; t < ntiles; t++) {
        __syncthreads();
        for (int idx = threadIdx.x; idx < 64 * 16; idx += 256) {
            int r = idx >> 4, c4 = idx & 15;
            size_t gro = (size_t)(b * SEQ + t * 64 + r) * QKVN + hk * DH + c4 * 4;
            *(float4*)&Ks[r][c4 * 4] = *(const float4*)(qkv + gro + QDIM);
            *(float4*)&Vs[r][c4 * 4] = *(const float4*)(qkv + gro + QDIM + KVDIM);
        }
        __syncthreads();
        int jmax = min(64, i - t * 64 + 1);
        for (int jj = 0; jj < jmax; jj++) {
            float s = q0 * Ks[jj][lane] + q1 * Ks[jj][lane + 32];
            #pragma unroll
            for (int o = 16; o; o >>= 1) s += __shfl_xor_sync(0xffffffffu, s, o);
            s *= 0.125f;
            float mn = fmaxf(m, s);
            float corr = __expf(m - mn);
            float p = __expf(s - mn);
            lsum = lsum * corr + p;
            acc0 = acc0 * corr + p * Vs[jj][lane];
            acc1 = acc1 * corr + p * Vs[jj][lane + 32];
            m = mn;
        }
    }
    float invl = 1.f / lsum;
    float o0 = acc0 * invl, o1 = acc1 * invl;
    size_t ob = (size_t)(b * SEQ + i) * QDIM + hq * DH;
    __nv_bfloat16 h0 = __float2bfloat16(o0), h1 = __float2bfloat16(o1);
    oh[ob + lane]      = h0;
    ol[ob + lane]      = __float2bfloat16(o0 - __bfloat162float(h0));
    oh[ob + lane + 32] = h1;
    ol[ob + lane + 32] = __float2bfloat16(o1 - __bfloat162float(h1));
}

// ---------------- SiLU(gate)*up with fused bf16 split ----------------
__global__ void silu_split(const float* __restrict__ gu,
                           __nv_bfloat16* __restrict__ oh, __nv_bfloat16* __restrict__ ol) {
    int n = MROWS * FF;
    for (int i = blockIdx.x * blockDim.x + threadIdx.x; i < n; i += gridDim.x * blockDim.x) {
        int r = i / FF, c = i - r * FF;
        float g = gu[(size_t)r * (2 * FF) + c];
        float u = gu[(size_t)r * (2 * FF) + FF + c];
        float y = (g / (1.f + __expf(-g))) * u;
        __nv_bfloat16 h = __float2bfloat16(y);
        oh[i] = h;
        ol[i] = __float2bfloat16(y - __bfloat162float(h));
    }
}

// ---------------- host driver ----------------
extern "C" void kernel_launch(void* const* d_in, const int* in_sizes, int n_in,
                              void* d_out, int out_size) {
    (void)in_sizes; (void)n_in; (void)out_size;
    const float* prefix = (const float*)d_in[0];
    const float* ln1    = (const float*)d_in[1];
    const float* wq     = (const float*)d_in[2];
    const float* wk     = (const float*)d_in[3];
    const float* wv     = (const float*)d_in[4];
    const float* wo     = (const float*)d_in[5];
    const float* ln2    = (const float*)d_in[6];
    const float* wg     = (const float*)d_in[7];
    const float* wu     = (const float*)d_in[8];
    const float* wd     = (const float*)d_in[9];
    const int*   pos    = (const int*)d_in[11];
    float* h = (float*)d_out;

    __nv_bfloat16 *hn_h, *hn_l, *at_h, *at_l, *ac_h, *ac_l;
    __nv_bfloat16 *wqkv_h, *wqkv_l, *wo_h, *wo_l, *wgu_h, *wgu_l, *wd_h, *wd_l;
    float *qkv, *gu;
    cudaGetSymbolAddress((void**)&hn_h, g_hn_h);
    cudaGetSymbolAddress((void**)&hn_l, g_hn_l);
    cudaGetSymbolAddress((void**)&qkv,  g_qkv);
    cudaGetSymbolAddress((void**)&at_h, g_at_h);
    cudaGetSymbolAddress((void**)&at_l, g_at_l);
    cudaGetSymbolAddress((void**)&gu,   g_gu);
    cudaGetSymbolAddress((void**)&ac_h, g_ac_h);
    cudaGetSymbolAddress((void**)&ac_l, g_ac_l);
    cudaGetSymbolAddress((void**)&wqkv_h, g_wqkv_h);
    cudaGetSymbolAddress((void**)&wqkv_l, g_wqkv_l);
    cudaGetSymbolAddress((void**)&wo_h,   g_wo_h);
    cudaGetSymbolAddress((void**)&wo_l,   g_wo_l);
    cudaGetSymbolAddress((void**)&wgu_h,  g_wgu_h);
    cudaGetSymbolAddress((void**)&wgu_l,  g_wgu_l);
    cudaGetSymbolAddress((void**)&wd_h,   g_wd_h);
    cudaGetSymbolAddress((void**)&wd_l,   g_wd_l);

    cudaFuncSetAttribute(mma_gemm<0>, cudaFuncAttributeMaxDynamicSharedMemorySize, GEMM_SMEM);
    cudaFuncSetAttribute(mma_gemm<1>, cudaFuncAttributeMaxDynamicSharedMemorySize, GEMM_SMEM);

    cudaMemcpyAsync(h, prefix, (size_t)MROWS * DMODEL * sizeof(float),
                    cudaMemcpyDeviceToDevice, 0);

    dim3 tb(32, 8);
    for (int l = 0; l < NLAYERS; l++) {
        const float* wq_l = wq + (size_t)l * DMODEL * QDIM;
        const float* wk_l = wk + (size_t)l * DMODEL * KVDIM;
        const float* wv_l = wv + (size_t)l * DMODEL * KVDIM;
        const float* wo_p = wo + (size_t)l * QDIM * DMODEL;
        const float* wg_l = wg + (size_t)l * DMODEL * FF;
        const float* wu_l = wu + (size_t)l * DMODEL * FF;
        const float* wd_p = wd + (size_t)l * FF * DMODEL;

        // weight transpose + split (into [N][K] bf16 hi/lo)
        wt_split<<<dim3(QDIM / 32, DMODEL / 32), tb>>>(wq_l, wqkv_h, wqkv_l, DMODEL, QDIM, DMODEL);
        wt_split<<<dim3(KVDIM / 32, DMODEL / 32), tb>>>(wk_l, wqkv_h + (size_t)QDIM * DMODEL,
                                                        wqkv_l + (size_t)QDIM * DMODEL, DMODEL, KVDIM, DMODEL);
        wt_split<<<dim3(KVDIM / 32, DMODEL / 32), tb>>>(wv_l, wqkv_h + (size_t)(QDIM + KVDIM) * DMODEL,
                                                        wqkv_l + (size_t)(QDIM + KVDIM) * DMODEL, DMODEL, KVDIM, DMODEL);
        wt_split<<<dim3(DMODEL / 32, QDIM / 32), tb>>>(wo_p, wo_h, wo_l, QDIM, DMODEL, QDIM);
        wt_split<<<dim3(FF / 32, DMODEL / 32), tb>>>(wg_l, wgu_h, wgu_l, DMODEL, FF, DMODEL);
        wt_split<<<dim3(FF / 32, DMODEL / 32), tb>>>(wu_l, wgu_h + (size_t)FF * DMODEL,
                                                     wgu_l + (size_t)FF * DMODEL, DMODEL, FF, DMODEL);
        wt_split<<<dim3(DMODEL / 32, FF / 32), tb>>>(wd_p, wd_h, wd_l, FF, DMODEL, FF);

        // attention block
        rmsnorm_split<<<MROWS, 256>>>(h, ln1 + (size_t)l * DMODEL, hn_h, hn_l);
        mma_gemm<0><<<dim3(QKVN / 64, MROWS / 128), 256, GEMM_SMEM>>>(hn_h, hn_l, wqkv_h, wqkv_l, qkv, QKVN, DMODEL);
        rope_kernel<<<(MROWS * HQ * 32 + 255) / 256, 256>>>(qkv, pos, HQ, 0);
        rope_kernel<<<(MROWS * HKV * 32 + 255) / 256, 256>>>(qkv, pos, HKV, QDIM);
        attn_kernel<<<dim3(SEQ / 8, BATCH * HQ), 256>>>(qkv, at_h, at_l);
        mma_gemm<1><<<dim3(DMODEL / 64, MROWS / 128), 256, GEMM_SMEM>>>(at_h, at_l, wo_h, wo_l, h, DMODEL, QDIM);

        // mlp block
        rmsnorm_split<<<MROWS, 256>>>(h, ln2 + (size_t)l * DMODEL, hn_h, hn_l);
        mma_gemm<0><<<dim3(2 * FF / 64, MROWS / 128), 256, GEMM_SMEM>>>(hn_h, hn_l, wgu_h, wgu_l, gu, 2 * FF, DMODEL);
        silu_split<<<2048, 256>>>(gu, ac_h, ac_l);
        mma_gemm<1><<<dim3(DMODEL / 64, MROWS / 128), 256, GEMM_SMEM>>>(ac_h, ac_l, wd_h, wd_l, h, DMODEL, FF);
    }
}